// round 14
// baseline (speedup 1.0000x reference)
#include <cuda_runtime.h>
#include <cuda_fp16.h>
#include <cstdint>

#define G     64
#define NVOX  (G*G*G)
#define INC   32
#define OUTC  64
#define PANE_ROWS   66
#define PANE_STRIDE 36   // words; 36 mod 32 = 4 -> frag LDS bank-conflict-free
#define CONV_SMEM   (6 * PANE_ROWS * PANE_STRIDE * 4)   // 57024 B

// ---- device scratch (allocation-free rule: static __device__ arrays) ----
__device__ float  g_voxsum[NVOX * INC];        // 32 MB: scatter sums (raw)
__device__ float  g_cnt[NVOX];                 //  1 MB: per-voxel point counts
__device__ float  g_invcnt[NVOX];              //  1 MB: cnt>0 ? 1/cnt : 0
__device__ __half g_conv[NVOX * OUTC];         // 32 MB: conv output (occ-masked, fp16)
__device__ float  g_wfrag[27 * 4 * 8 * 32 * 2]; // W_conv in mma B-fragment order (tf32)

__device__ __forceinline__ unsigned cvt_tf32(float f) {
    unsigned u;
    asm("cvt.rna.tf32.f32 %0, %1;" : "=r"(u) : "f"(f));
    return u;
}

__device__ __forceinline__ void mma_tf32(float c[4], unsigned a0, unsigned a1,
                                         unsigned a2, unsigned a3,
                                         unsigned b0, unsigned b1) {
    asm volatile(
        "mma.sync.aligned.m16n8k8.row.col.f32.tf32.tf32.f32 "
        "{%0,%1,%2,%3}, {%4,%5,%6,%7}, {%8,%9}, {%0,%1,%2,%3};"
        : "+f"(c[0]), "+f"(c[1]), "+f"(c[2]), "+f"(c[3])
        : "r"(a0), "r"(a1), "r"(a2), "r"(a3), "r"(b0), "r"(b1));
}

// ============================================================================
// 1) scatter-mean accumulate
// ============================================================================
__global__ void scatter_kernel(const float* __restrict__ pts,
                               const float* __restrict__ feats, int n) {
    int i = blockIdx.x * blockDim.x + threadIdx.x;
    if (i >= n) return;
    float px = pts[3 * i + 0];
    float py = pts[3 * i + 1];
    float pz = pts[3 * i + 2];
    int bx = (int)floorf(px);
    int by = (int)floorf(py);
    int bz = (int)floorf(pz);
    bx = min(max(bx, 0), G - 1);
    by = min(max(by, 0), G - 1);
    bz = min(max(bz, 0), G - 1);
    int fl = (bx * G + by) * G + bz;

    atomicAdd(&g_cnt[fl], 1.0f);

    const float4* f4 = (const float4*)(feats + (size_t)i * INC);
    float4* dst = (float4*)(g_voxsum + (size_t)fl * INC);
#pragma unroll
    for (int k = 0; k < INC / 4; k++) {
        float4 v = f4[k];
        atomicAdd(dst + k, v);
    }
}

// ============================================================================
// 1b) per-voxel inverse counts
// ============================================================================
__global__ void invcnt_kernel() {
    int v = blockIdx.x * blockDim.x + threadIdx.x;
    if (v >= NVOX) return;
    float c = g_cnt[v];
    g_invcnt[v] = (c > 0.0f) ? (1.0f / c) : 0.0f;
}

// ============================================================================
// 2) W_conv -> B-fragment layout (tf32-rounded)
// ============================================================================
__global__ void wfrag_kernel(const float* __restrict__ Wc) {
    int i = blockIdx.x * blockDim.x + threadIdx.x;   // (tap,ks,nt,lane)
    if (i >= 27 * 4 * 8 * 32) return;
    int lane = i & 31;
    int nt   = (i >> 5) & 7;
    int ks   = (i >> 8) & 3;
    int tap  = i >> 10;
    int ci = ks * 8 + (lane & 3);
    int co = nt * 8 + (lane >> 2);
    unsigned u0 = cvt_tf32(Wc[((size_t)tap * 32 + ci) * 64 + co]);
    unsigned u1 = cvt_tf32(Wc[((size_t)tap * 32 + ci + 4) * 64 + co]);
    g_wfrag[(size_t)i * 2 + 0] = __uint_as_float(u0);
    g_wfrag[(size_t)i * 2 + 1] = __uint_as_float(u1);
}

// ============================================================================
// 3) conv as implicit GEMM on tf32 mma.sync — 4-column CTA, full-N warp tile.
//    CTA = (x, 4 y-columns): 6 staged panes serve 4 columns (-25% staging).
//    8 warps = col(4) x mh(2); warp tile M=32 x N=64: each (tap,ks) B-frag
//    set (16 wf) feeds 16 MMAs -> 1.5 wf/MMA (was 2.0).
// ============================================================================
__global__ __launch_bounds__(256) void conv_kernel() {
    extern __shared__ unsigned pane[];   // 6 * PANE_ROWS * PANE_STRIDE words

    const int x  = blockIdx.x;
    const int y0 = blockIdx.y * 4;
    const int tid  = threadIdx.x;
    const int lane = tid & 31;
    const int warp = tid >> 5;
    const int col  = warp & 3;          // which y column (0..3)
    const int mh   = warp >> 2;         // z half: 0 -> z 0..31, 1 -> z 32..63
    const int z0w  = mh * 32;
    const int colbase = (x * G + y0 + col) * G;

    float acc[2][8][4];                 // [mt][nt][frag]
#pragma unroll
    for (int mt = 0; mt < 2; mt++)
#pragma unroll
        for (int nt = 0; nt < 8; nt++)
#pragma unroll
            for (int j = 0; j < 4; j++) acc[mt][nt][j] = 0.0f;

    const float2* wfp = (const float2*)g_wfrag;

#pragma unroll 1
    for (int dx = 0; dx < 3; dx++) {
        __syncthreads();
        int gx = x + dx - 1;
        // stage 6 y-panes (y0-1 .. y0+4) for this gx
        for (int i = tid; i < 6 * PANE_ROWS * 8; i += 256) {
            int c4  = i & 7;
            int row = (i >> 3) % PANE_ROWS;
            int p   = (i >> 3) / PANE_ROWS;
            int gy = y0 + p - 1;
            int gz = row - 1;
            float4 v = make_float4(0.f, 0.f, 0.f, 0.f);
            if ((unsigned)gx < G && (unsigned)gy < G && (unsigned)gz < G) {
                int vox = (gx * G + gy) * G + gz;
                v = *(const float4*)(g_voxsum + ((size_t)vox << 5) + c4 * 4);
                float inv = g_invcnt[vox];
                v.x *= inv; v.y *= inv; v.z *= inv; v.w *= inv;
            }
            unsigned* dst = pane + (p * PANE_ROWS + row) * PANE_STRIDE + c4 * 4;
            dst[0] = cvt_tf32(v.x);
            dst[1] = cvt_tf32(v.y);
            dst[2] = cvt_tf32(v.z);
            dst[3] = cvt_tf32(v.w);
        }
        __syncthreads();

#pragma unroll 1
        for (int dy = 0; dy < 3; dy++) {
            const unsigned* pb = pane + (col + dy) * PANE_ROWS * PANE_STRIDE;
#pragma unroll 1
            for (int dz = 0; dz < 3; dz++) {
                int tap = (dx * 3 + dy) * 3 + dz;
#pragma unroll
                for (int ks = 0; ks < 4; ks++) {
                    // B frags for this (tap, ks): 8 x LDG.64, reused by 2 m-tiles
                    float2 bf[8];
#pragma unroll
                    for (int nt = 0; nt < 8; nt++)
                        bf[nt] = wfp[((size_t)(tap * 4 + ks) * 8 + nt) * 32 + lane];

                    int cola = ks * 8 + (lane & 3);
#pragma unroll
                    for (int mt = 0; mt < 2; mt++) {
                        int rowa = z0w + mt * 16 + dz + (lane >> 2);
                        const unsigned* ap = pb + rowa * PANE_STRIDE + cola;
                        unsigned a0 = ap[0];
                        unsigned a1 = ap[8 * PANE_STRIDE];
                        unsigned a2 = ap[4];
                        unsigned a3 = ap[8 * PANE_STRIDE + 4];
#pragma unroll
                        for (int nt = 0; nt < 8; nt++)
                            mma_tf32(acc[mt][nt], a0, a1, a2, a3,
                                     __float_as_uint(bf[nt].x),
                                     __float_as_uint(bf[nt].y));
                    }
                }
            }
        }
    }

#pragma unroll
    for (int mt = 0; mt < 2; mt++) {
        int z1 = z0w + mt * 16 + (lane >> 2);
        int z2 = z1 + 8;
        float occ1 = (g_invcnt[colbase + z1] > 0.0f) ? 1.0f : 0.0f;
        float occ2 = (g_invcnt[colbase + z2] > 0.0f) ? 1.0f : 0.0f;
#pragma unroll
        for (int nt = 0; nt < 8; nt++) {
            int co = nt * 8 + (lane & 3) * 2;
            __half2 v1 = __floats2half2_rn(acc[mt][nt][0] * occ1, acc[mt][nt][1] * occ1);
            __half2 v2 = __floats2half2_rn(acc[mt][nt][2] * occ2, acc[mt][nt][3] * occ2);
            *(__half2*)(g_conv + (size_t)(colbase + z1) * OUTC + co) = v1;
            *(__half2*)(g_conv + (size_t)(colbase + z2) * OUTC + co) = v2;
        }
    }
}

// ============================================================================
// 4a) residual linear as tf32 MMA (R10 measured: 93us)
// ============================================================================
__global__ __launch_bounds__(256) void residual_kernel(const float* __restrict__ feats,
                                                       const float* __restrict__ Wlin,
                                                       const float* __restrict__ blin,
                                                       float* __restrict__ out, int n) {
    __shared__ uint2 bsm[8 * 4 * 32];   // [nt][ks][lane]  8KB
    __shared__ float2 bbias[8 * 4];     // [nt][tig]

    const int tid  = threadIdx.x;
    const int lane = tid & 31;
    const int warp = tid >> 5;

    for (int i = tid; i < 8 * 4 * 32; i += 256) {
        int l  = i & 31;
        int ks = (i >> 5) & 3;
        int nt = i >> 7;
        int k = ks * 8 + (l & 3);
        int nn = nt * 8 + (l >> 2);
        uint2 b;
        b.x = cvt_tf32(Wlin[(size_t)nn * INC + k]);
        b.y = cvt_tf32(Wlin[(size_t)nn * INC + k + 4]);
        bsm[i] = b;
    }
    if (tid < 32) {
        int nt = tid >> 2, tig = tid & 3;
        bbias[nt * 4 + tig] = make_float2(blin[nt * 8 + 2 * tig], blin[nt * 8 + 2 * tig + 1]);
    }
    __syncthreads();

    const int gwarp  = blockIdx.x * 8 + warp;
    const int nwarps = gridDim.x * 8;
    const int ntiles = (n + 15) >> 4;
    const int gid = lane >> 2;
    const int tig = lane & 3;

    for (int tile = gwarp; tile < ntiles; tile += nwarps) {
        int p0 = tile * 16;
        int pr1 = p0 + gid;
        int pr2 = p0 + gid + 8;
        bool v1 = pr1 < n, v2 = pr2 < n;
        const float* f1 = feats + (size_t)pr1 * INC;
        const float* f2 = feats + (size_t)pr2 * INC;

        float acc[8][4];
#pragma unroll
        for (int nt = 0; nt < 8; nt++) {
            float2 bb = bbias[nt * 4 + tig];
            acc[nt][0] = bb.x; acc[nt][1] = bb.y;
            acc[nt][2] = bb.x; acc[nt][3] = bb.y;
        }

#pragma unroll
        for (int ks = 0; ks < 4; ks++) {
            int c = ks * 8 + tig;
            unsigned a0 = v1 ? cvt_tf32(f1[c])     : 0u;
            unsigned a1 = v2 ? cvt_tf32(f2[c])     : 0u;
            unsigned a2 = v1 ? cvt_tf32(f1[c + 4]) : 0u;
            unsigned a3 = v2 ? cvt_tf32(f2[c + 4]) : 0u;
#pragma unroll
            for (int nt = 0; nt < 8; nt++) {
                uint2 b = bsm[(nt * 4 + ks) * 32 + lane];
                mma_tf32(acc[nt], a0, a1, a2, a3, b.x, b.y);
            }
        }

        if (v1) {
            float2* o1 = (float2*)(out + (size_t)pr1 * OUTC);
#pragma unroll
            for (int nt = 0; nt < 8; nt++)
                o1[nt * 4 + tig] = make_float2(acc[nt][0], acc[nt][1]);
        }
        if (v2) {
            float2* o2 = (float2*)(out + (size_t)pr2 * OUTC);
#pragma unroll
            for (int nt = 0; nt < 8; nt++)
                o2[nt * 4 + tig] = make_float2(acc[nt][2], acc[nt][3]);
        }
    }
}

// ============================================================================
// 4b) trilinear devoxelize: two points per warp, 16 lanes per point (R13: ~95us)
// ============================================================================
__global__ __launch_bounds__(256) void devox_kernel(const float* __restrict__ pts,
                                                    float* __restrict__ out, int n) {
    const int lane   = threadIdx.x & 31;
    const int gwarp  = (blockIdx.x * blockDim.x + threadIdx.x) >> 5;
    const int nwarps = (gridDim.x * blockDim.x) >> 5;
    const int half   = lane >> 4;
    const int sl     = lane & 15;

    for (int p0 = gwarp * 2; p0 < n; p0 += nwarps * 2) {
        int p = p0 + half;
        bool valid = p < n;
        int ps = valid ? p : (n - 1);

        float px = pts[3 * ps + 0];
        float py = pts[3 * ps + 1];
        float pz = pts[3 * ps + 2];
        int bx = (int)floorf(px);
        int by = (int)floorf(py);
        int bz = (int)floorf(pz);
        float fx = px - (float)bx;
        float fy = py - (float)by;
        float fz = pz - (float)bz;

        float4* orow = (float4*)(out + (size_t)ps * OUTC);
        float4 acc = orow[sl];

#pragma unroll
        for (int c = 0; c < 8; c++) {
            int dx = (c >> 2) & 1, dy = (c >> 1) & 1, dz = c & 1;
            int nx = bx + dx, ny = by + dy, nz = bz + dz;
            float w = (dx ? fx : 1.0f - fx) * (dy ? fy : 1.0f - fy) * (dz ? fz : 1.0f - fz);
            if ((unsigned)nx < G && (unsigned)ny < G && (unsigned)nz < G) {
                int fl = (nx * G + ny) * G + nz;
                const uint2* row = (const uint2*)(g_conv + (size_t)fl * OUTC);
                uint2 v = row[sl];
                float2 f0 = __half22float2(*(const __half2*)&v.x);
                float2 f1 = __half22float2(*(const __half2*)&v.y);
                acc.x += w * f0.x;
                acc.y += w * f0.y;
                acc.z += w * f1.x;
                acc.w += w * f1.y;
            }
        }

        if (valid) orow[sl] = acc;
    }
}

// ============================================================================
extern "C" void kernel_launch(void* const* d_in, const int* in_sizes, int n_in,
                              void* d_out, int out_size) {
    const float* pts   = (const float*)d_in[0];
    const float* feats = (const float*)d_in[1];
    const float* Wc    = (const float*)d_in[2];
    const float* Wl    = (const float*)d_in[3];
    const float* bl    = (const float*)d_in[4];
    float* out = (float*)d_out;
    int npts = in_sizes[0] / 3;

    static bool attr_set = false;
    if (!attr_set) {   // host-side attribute, idempotent, capture-safe
        cudaFuncSetAttribute(conv_kernel,
                             cudaFuncAttributeMaxDynamicSharedMemorySize, CONV_SMEM);
        attr_set = true;
    }

    void *p_sum = nullptr, *p_cnt = nullptr;
    cudaGetSymbolAddress(&p_sum, g_voxsum);
    cudaGetSymbolAddress(&p_cnt, g_cnt);
    cudaMemsetAsync(p_sum, 0, (size_t)NVOX * INC * sizeof(float));
    cudaMemsetAsync(p_cnt, 0, (size_t)NVOX * sizeof(float));

    scatter_kernel<<<(npts + 255) / 256, 256>>>(pts, feats, npts);

    invcnt_kernel<<<NVOX / 256, 256>>>();

    wfrag_kernel<<<(27 * 4 * 8 * 32 + 255) / 256, 256>>>(Wc);

    dim3 cgrid(G, G / 4);
    conv_kernel<<<cgrid, 256, CONV_SMEM>>>();

    residual_kernel<<<2048, 256>>>(feats, Wl, bl, out, npts);

    devox_kernel<<<4096, 256>>>(pts, out, npts);
}

// round 15
// speedup vs baseline: 1.0765x; 1.0765x over previous
#include <cuda_runtime.h>
#include <cuda_fp16.h>
#include <cstdint>

#define G     64
#define NVOX  (G*G*G)
#define INC   32
#define OUTC  64
#define PANE_ROWS   66
#define PANE_STRIDE 36   // words; 36 mod 32 = 4 -> frag LDS bank-conflict-free

// ---- device scratch (allocation-free rule: static __device__ arrays) ----
__device__ float  g_voxsum[NVOX * INC];        // 32 MB: scatter sums (raw)
__device__ float  g_cnt[NVOX];                 //  1 MB: per-voxel point counts
__device__ float  g_invcnt[NVOX];              //  1 MB: cnt>0 ? 1/cnt : 0
__device__ __half g_conv[NVOX * OUTC];         // 32 MB: conv output (occ-masked, fp16)
__device__ float  g_wfrag[27 * 4 * 8 * 32 * 2]; // W_conv in mma B-fragment order (tf32)

__device__ __forceinline__ unsigned cvt_tf32(float f) {
    unsigned u;
    asm("cvt.rna.tf32.f32 %0, %1;" : "=r"(u) : "f"(f));
    return u;
}

__device__ __forceinline__ void mma_tf32(float c[4], unsigned a0, unsigned a1,
                                         unsigned a2, unsigned a3,
                                         unsigned b0, unsigned b1) {
    asm volatile(
        "mma.sync.aligned.m16n8k8.row.col.f32.tf32.tf32.f32 "
        "{%0,%1,%2,%3}, {%4,%5,%6,%7}, {%8,%9}, {%0,%1,%2,%3};"
        : "+f"(c[0]), "+f"(c[1]), "+f"(c[2]), "+f"(c[3])
        : "r"(a0), "r"(a1), "r"(a2), "r"(a3), "r"(b0), "r"(b1));
}

// ============================================================================
// 1) scatter-mean accumulate
// ============================================================================
__global__ void scatter_kernel(const float* __restrict__ pts,
                               const float* __restrict__ feats, int n) {
    int i = blockIdx.x * blockDim.x + threadIdx.x;
    if (i >= n) return;
    float px = pts[3 * i + 0];
    float py = pts[3 * i + 1];
    float pz = pts[3 * i + 2];
    int bx = (int)floorf(px);
    int by = (int)floorf(py);
    int bz = (int)floorf(pz);
    bx = min(max(bx, 0), G - 1);
    by = min(max(by, 0), G - 1);
    bz = min(max(bz, 0), G - 1);
    int fl = (bx * G + by) * G + bz;

    atomicAdd(&g_cnt[fl], 1.0f);

    const float4* f4 = (const float4*)(feats + (size_t)i * INC);
    float4* dst = (float4*)(g_voxsum + (size_t)fl * INC);
#pragma unroll
    for (int k = 0; k < INC / 4; k++) {
        float4 v = f4[k];
        atomicAdd(dst + k, v);
    }
}

// ============================================================================
// 1b) per-voxel inverse counts
// ============================================================================
__global__ void invcnt_kernel() {
    int v = blockIdx.x * blockDim.x + threadIdx.x;
    if (v >= NVOX) return;
    float c = g_cnt[v];
    g_invcnt[v] = (c > 0.0f) ? (1.0f / c) : 0.0f;
}

// ============================================================================
// 2) W_conv -> B-fragment layout (tf32-rounded)
// ============================================================================
__global__ void wfrag_kernel(const float* __restrict__ Wc) {
    int i = blockIdx.x * blockDim.x + threadIdx.x;   // (tap,ks,nt,lane)
    if (i >= 27 * 4 * 8 * 32) return;
    int lane = i & 31;
    int nt   = (i >> 5) & 7;
    int ks   = (i >> 8) & 3;
    int tap  = i >> 10;
    int ci = ks * 8 + (lane & 3);
    int co = nt * 8 + (lane >> 2);
    unsigned u0 = cvt_tf32(Wc[((size_t)tap * 32 + ci) * 64 + co]);
    unsigned u1 = cvt_tf32(Wc[((size_t)tap * 32 + ci + 4) * 64 + co]);
    g_wfrag[(size_t)i * 2 + 0] = __uint_as_float(u0);
    g_wfrag[(size_t)i * 2 + 1] = __uint_as_float(u1);
}

// ============================================================================
// 3) conv as implicit GEMM on tf32 mma.sync — 2-column CTA (R12 exact: 177us;
//    the 4-column variant regressed to 240us on occupancy collapse)
// ============================================================================
__global__ __launch_bounds__(256) void conv_kernel() {
    __shared__ unsigned pane[4 * PANE_ROWS * PANE_STRIDE];   // 38016 B

    const int x  = blockIdx.x;
    const int y0 = blockIdx.y * 2;
    const int tid  = threadIdx.x;
    const int lane = tid & 31;
    const int warp = tid >> 5;
    const int col  = warp & 1;
    const int mh   = (warp >> 1) & 1;
    const int nh   = warp >> 2;
    const int z0w  = mh * 32;
    const int colbase = (x * G + y0 + col) * G;

    float acc[2][4][4];
#pragma unroll
    for (int mt = 0; mt < 2; mt++)
#pragma unroll
        for (int nt = 0; nt < 4; nt++)
#pragma unroll
            for (int j = 0; j < 4; j++) acc[mt][nt][j] = 0.0f;

    const float2* wfp = (const float2*)g_wfrag;

#pragma unroll 1
    for (int dx = 0; dx < 3; dx++) {
        __syncthreads();
        int gx = x + dx - 1;
        for (int i = tid; i < 4 * PANE_ROWS * 8; i += 256) {
            int c4  = i & 7;
            int row = (i >> 3) % PANE_ROWS;
            int p   = (i >> 3) / PANE_ROWS;
            int gy = y0 + p - 1;
            int gz = row - 1;
            float4 v = make_float4(0.f, 0.f, 0.f, 0.f);
            if ((unsigned)gx < G && (unsigned)gy < G && (unsigned)gz < G) {
                int vox = (gx * G + gy) * G + gz;
                v = *(const float4*)(g_voxsum + ((size_t)vox << 5) + c4 * 4);
                float inv = g_invcnt[vox];
                v.x *= inv; v.y *= inv; v.z *= inv; v.w *= inv;
            }
            unsigned* dst = pane + (p * PANE_ROWS + row) * PANE_STRIDE + c4 * 4;
            dst[0] = cvt_tf32(v.x);
            dst[1] = cvt_tf32(v.y);
            dst[2] = cvt_tf32(v.z);
            dst[3] = cvt_tf32(v.w);
        }
        __syncthreads();

#pragma unroll 1
        for (int dy = 0; dy < 3; dy++) {
            const unsigned* pb = pane + (col + dy) * PANE_ROWS * PANE_STRIDE;
#pragma unroll 1
            for (int dz = 0; dz < 3; dz++) {
                int tap = (dx * 3 + dy) * 3 + dz;
#pragma unroll
                for (int ks = 0; ks < 4; ks++) {
                    float2 bf[4];
#pragma unroll
                    for (int nt = 0; nt < 4; nt++)
                        bf[nt] = wfp[((size_t)(tap * 4 + ks) * 8 + nh * 4 + nt) * 32 + lane];

                    int cola = ks * 8 + (lane & 3);
#pragma unroll
                    for (int mt = 0; mt < 2; mt++) {
                        int rowa = z0w + mt * 16 + dz + (lane >> 2);
                        const unsigned* ap = pb + rowa * PANE_STRIDE + cola;
                        unsigned a0 = ap[0];
                        unsigned a1 = ap[8 * PANE_STRIDE];
                        unsigned a2 = ap[4];
                        unsigned a3 = ap[8 * PANE_STRIDE + 4];
#pragma unroll
                        for (int nt = 0; nt < 4; nt++)
                            mma_tf32(acc[mt][nt], a0, a1, a2, a3,
                                     __float_as_uint(bf[nt].x),
                                     __float_as_uint(bf[nt].y));
                    }
                }
            }
        }
    }

#pragma unroll
    for (int mt = 0; mt < 2; mt++) {
        int z1 = z0w + mt * 16 + (lane >> 2);
        int z2 = z1 + 8;
        float occ1 = (g_invcnt[colbase + z1] > 0.0f) ? 1.0f : 0.0f;
        float occ2 = (g_invcnt[colbase + z2] > 0.0f) ? 1.0f : 0.0f;
#pragma unroll
        for (int nt = 0; nt < 4; nt++) {
            int co = nh * 32 + nt * 8 + (lane & 3) * 2;
            __half2 v1 = __floats2half2_rn(acc[mt][nt][0] * occ1, acc[mt][nt][1] * occ1);
            __half2 v2 = __floats2half2_rn(acc[mt][nt][2] * occ2, acc[mt][nt][3] * occ2);
            *(__half2*)(g_conv + (size_t)(colbase + z1) * OUTC + co) = v1;
            *(__half2*)(g_conv + (size_t)(colbase + z2) * OUTC + co) = v2;
        }
    }
}

// ============================================================================
// 4a) residual linear as tf32 MMA (R10 measured: 93us) — runs on side stream
// ============================================================================
__global__ __launch_bounds__(256) void residual_kernel(const float* __restrict__ feats,
                                                       const float* __restrict__ Wlin,
                                                       const float* __restrict__ blin,
                                                       float* __restrict__ out, int n) {
    __shared__ uint2 bsm[8 * 4 * 32];   // [nt][ks][lane]  8KB
    __shared__ float2 bbias[8 * 4];     // [nt][tig]

    const int tid  = threadIdx.x;
    const int lane = tid & 31;
    const int warp = tid >> 5;

    for (int i = tid; i < 8 * 4 * 32; i += 256) {
        int l  = i & 31;
        int ks = (i >> 5) & 3;
        int nt = i >> 7;
        int k = ks * 8 + (l & 3);
        int nn = nt * 8 + (l >> 2);
        uint2 b;
        b.x = cvt_tf32(Wlin[(size_t)nn * INC + k]);
        b.y = cvt_tf32(Wlin[(size_t)nn * INC + k + 4]);
        bsm[i] = b;
    }
    if (tid < 32) {
        int nt = tid >> 2, tig = tid & 3;
        bbias[nt * 4 + tig] = make_float2(blin[nt * 8 + 2 * tig], blin[nt * 8 + 2 * tig + 1]);
    }
    __syncthreads();

    const int gwarp  = blockIdx.x * 8 + warp;
    const int nwarps = gridDim.x * 8;
    const int ntiles = (n + 15) >> 4;
    const int gid = lane >> 2;
    const int tig = lane & 3;

    for (int tile = gwarp; tile < ntiles; tile += nwarps) {
        int p0 = tile * 16;
        int pr1 = p0 + gid;
        int pr2 = p0 + gid + 8;
        bool v1 = pr1 < n, v2 = pr2 < n;
        const float* f1 = feats + (size_t)pr1 * INC;
        const float* f2 = feats + (size_t)pr2 * INC;

        float acc[8][4];
#pragma unroll
        for (int nt = 0; nt < 8; nt++) {
            float2 bb = bbias[nt * 4 + tig];
            acc[nt][0] = bb.x; acc[nt][1] = bb.y;
            acc[nt][2] = bb.x; acc[nt][3] = bb.y;
        }

#pragma unroll
        for (int ks = 0; ks < 4; ks++) {
            int c = ks * 8 + tig;
            unsigned a0 = v1 ? cvt_tf32(f1[c])     : 0u;
            unsigned a1 = v2 ? cvt_tf32(f2[c])     : 0u;
            unsigned a2 = v1 ? cvt_tf32(f1[c + 4]) : 0u;
            unsigned a3 = v2 ? cvt_tf32(f2[c + 4]) : 0u;
#pragma unroll
            for (int nt = 0; nt < 8; nt++) {
                uint2 b = bsm[(nt * 4 + ks) * 32 + lane];
                mma_tf32(acc[nt], a0, a1, a2, a3, b.x, b.y);
            }
        }

        if (v1) {
            float2* o1 = (float2*)(out + (size_t)pr1 * OUTC);
#pragma unroll
            for (int nt = 0; nt < 8; nt++)
                o1[nt * 4 + tig] = make_float2(acc[nt][0], acc[nt][1]);
        }
        if (v2) {
            float2* o2 = (float2*)(out + (size_t)pr2 * OUTC);
#pragma unroll
            for (int nt = 0; nt < 8; nt++)
                o2[nt * 4 + tig] = make_float2(acc[nt][2], acc[nt][3]);
        }
    }
}

// ============================================================================
// 4b) trilinear devoxelize: two points per warp, 16 lanes per point (R13: ~95us)
// ============================================================================
__global__ __launch_bounds__(256) void devox_kernel(const float* __restrict__ pts,
                                                    float* __restrict__ out, int n) {
    const int lane   = threadIdx.x & 31;
    const int gwarp  = (blockIdx.x * blockDim.x + threadIdx.x) >> 5;
    const int nwarps = (gridDim.x * blockDim.x) >> 5;
    const int half   = lane >> 4;
    const int sl     = lane & 15;

    for (int p0 = gwarp * 2; p0 < n; p0 += nwarps * 2) {
        int p = p0 + half;
        bool valid = p < n;
        int ps = valid ? p : (n - 1);

        float px = pts[3 * ps + 0];
        float py = pts[3 * ps + 1];
        float pz = pts[3 * ps + 2];
        int bx = (int)floorf(px);
        int by = (int)floorf(py);
        int bz = (int)floorf(pz);
        float fx = px - (float)bx;
        float fy = py - (float)by;
        float fz = pz - (float)bz;

        float4* orow = (float4*)(out + (size_t)ps * OUTC);
        float4 acc = orow[sl];

#pragma unroll
        for (int c = 0; c < 8; c++) {
            int dx = (c >> 2) & 1, dy = (c >> 1) & 1, dz = c & 1;
            int nx = bx + dx, ny = by + dy, nz = bz + dz;
            float w = (dx ? fx : 1.0f - fx) * (dy ? fy : 1.0f - fy) * (dz ? fz : 1.0f - fz);
            if ((unsigned)nx < G && (unsigned)ny < G && (unsigned)nz < G) {
                int fl = (nx * G + ny) * G + nz;
                const uint2* row = (const uint2*)(g_conv + (size_t)fl * OUTC);
                uint2 v = row[sl];
                float2 f0 = __half22float2(*(const __half2*)&v.x);
                float2 f1 = __half22float2(*(const __half2*)&v.y);
                acc.x += w * f0.x;
                acc.y += w * f0.y;
                acc.z += w * f1.x;
                acc.w += w * f1.y;
            }
        }

        if (valid) orow[sl] = acc;
    }
}

// ============================================================================
extern "C" void kernel_launch(void* const* d_in, const int* in_sizes, int n_in,
                              void* d_out, int out_size) {
    const float* pts   = (const float*)d_in[0];
    const float* feats = (const float*)d_in[1];
    const float* Wc    = (const float*)d_in[2];
    const float* Wl    = (const float*)d_in[3];
    const float* bl    = (const float*)d_in[4];
    float* out = (float*)d_out;
    int npts = in_sizes[0] / 3;

    // one-time side-stream/event creation (host objects, no device memory)
    static cudaStream_t s_side = nullptr;
    static cudaEvent_t ev_root = nullptr, ev_side = nullptr;
    if (s_side == nullptr) {
        cudaStreamCreateWithFlags(&s_side, cudaStreamNonBlocking);
        cudaEventCreateWithFlags(&ev_root, cudaEventDisableTiming);
        cudaEventCreateWithFlags(&ev_side, cudaEventDisableTiming);
    }

    void *p_sum = nullptr, *p_cnt = nullptr;
    cudaGetSymbolAddress(&p_sum, g_voxsum);
    cudaGetSymbolAddress(&p_cnt, g_cnt);

    // ---- fork: side stream runs wfrag + residual (independent of scatter/conv)
    cudaEventRecord(ev_root, 0);
    cudaStreamWaitEvent(s_side, ev_root, 0);
    wfrag_kernel<<<(27 * 4 * 8 * 32 + 255) / 256, 256, 0, s_side>>>(Wc);
    residual_kernel<<<2048, 256, 0, s_side>>>(feats, Wl, bl, out, npts);
    cudaEventRecord(ev_side, s_side);

    // ---- main stream: voxelize -> conv
    cudaMemsetAsync(p_sum, 0, (size_t)NVOX * INC * sizeof(float));
    cudaMemsetAsync(p_cnt, 0, (size_t)NVOX * sizeof(float));

    scatter_kernel<<<(npts + 255) / 256, 256>>>(pts, feats, npts);

    invcnt_kernel<<<NVOX / 256, 256>>>();

    dim3 cgrid(G, G / 2);
    conv_kernel<<<cgrid, 256>>>();   // needs wfrag done; side stream finishes
                                     // wfrag (~5us) long before conv starts
    // ---- join: devox needs both conv (main) and residual (side)
    cudaStreamWaitEvent(0, ev_side, 0);
    devox_kernel<<<4096, 256>>>(pts, out, npts);
}